// round 15
// baseline (speedup 1.0000x reference)
#include <cuda_runtime.h>
#include <cuda_fp16.h>
#include <cstdint>
#include <math.h>

#define BB   2
#define SS   4096
#define DD   2048
#define HH   16
#define KVHH 4
#define HDD  128
#define NREP 4
#define KVSTR (2 * KVHH * HDD)   // 1024 halves: combined k|v row

// -------- scratch (device globals; no allocation allowed) --------
__device__ __half g_xh[(long)BB * SS * DD];
__device__ __half g_wqh[(long)DD * DD];
__device__ __half g_wkv[(long)DD * KVSTR];
__device__ __half g_woh[(long)DD * DD];
__device__ __half g_qh[(long)BB * SS * HH * HDD];
__device__ __half g_kvh[(long)BB * SS * KVSTR];
__device__ __half g_ah[(long)BB * SS * HH * HDD];

// ===================== helpers ==============================================
__device__ __forceinline__ uint32_t smem_u32(const void* p) {
    uint32_t a;
    asm("{ .reg .u64 t; cvta.to.shared.u64 t, %1; cvt.u32.u64 %0, t; }"
        : "=r"(a) : "l"(p));
    return a;
}
__device__ __forceinline__ void ldsm_x4(uint32_t r[4], uint32_t addr) {
    asm volatile("ldmatrix.sync.aligned.m8n8.x4.shared.b16 {%0,%1,%2,%3}, [%4];"
        : "=r"(r[0]), "=r"(r[1]), "=r"(r[2]), "=r"(r[3]) : "r"(addr));
}
__device__ __forceinline__ void ldsm_x4_t(uint32_t r[4], uint32_t addr) {
    asm volatile("ldmatrix.sync.aligned.m8n8.x4.trans.shared.b16 {%0,%1,%2,%3}, [%4];"
        : "=r"(r[0]), "=r"(r[1]), "=r"(r[2]), "=r"(r[3]) : "r"(addr));
}
__device__ __forceinline__ void mma_f16(float c[4], const uint32_t a[4],
                                        const uint32_t b0, const uint32_t b1) {
    asm volatile(
        "mma.sync.aligned.m16n8k16.row.col.f32.f16.f16.f32 "
        "{%0,%1,%2,%3}, {%4,%5,%6,%7}, {%8,%9}, {%0,%1,%2,%3};"
        : "+f"(c[0]), "+f"(c[1]), "+f"(c[2]), "+f"(c[3])
        : "r"(a[0]), "r"(a[1]), "r"(a[2]), "r"(a[3]), "r"(b0), "r"(b1));
}
__device__ __forceinline__ uint32_t pack_h2(float lo, float hi) {
    __half2 h = __floats2half2_rn(lo, hi);
    return *(uint32_t*)&h;
}

#define CP_ASYNC16(saddr, gptr) \
    asm volatile("cp.async.cg.shared.global [%0], [%1], 16;" \
                 :: "r"(saddr), "l"(gptr))
#define CP_COMMIT() asm volatile("cp.async.commit_group;" ::: "memory")
#define CP_WAIT0()  asm volatile("cp.async.wait_group 0;" ::: "memory")
#define CP_WAIT2()  asm volatile("cp.async.wait_group 2;" ::: "memory")

// ===================== fused float->half conversion =========================
#define N8_X  ((long)BB * SS * DD / 8)
#define N8_WQ ((long)DD * DD / 8)
#define N8_WO ((long)DD * DD / 8)
#define N8_WK ((long)DD * (KVHH * HDD) / 8)
#define N8_TOT (N8_X + N8_WQ + N8_WO + 2 * N8_WK)

__device__ __forceinline__ void cvt8(const float* in, __half* out, float s) {
    const float4* p = (const float4*)in;
    float4 v0 = p[0], v1 = p[1];
    __half h[8];
    h[0] = __float2half_rn(v0.x * s); h[1] = __float2half_rn(v0.y * s);
    h[2] = __float2half_rn(v0.z * s); h[3] = __float2half_rn(v0.w * s);
    h[4] = __float2half_rn(v1.x * s); h[5] = __float2half_rn(v1.y * s);
    h[6] = __float2half_rn(v1.z * s); h[7] = __float2half_rn(v1.w * s);
    *(uint4*)out = *(uint4*)h;
}

__global__ void cvt_all_kernel(const float* __restrict__ x,
                               const float* __restrict__ wq,
                               const float* __restrict__ wo,
                               const float* __restrict__ wk,
                               const float* __restrict__ wv,
                               float qscale)
{
    long i = (long)blockIdx.x * blockDim.x + threadIdx.x;
    if (i >= N8_TOT) return;
    if (i < N8_X) {
        cvt8(x + i * 8, g_xh + i * 8, 1.0f);
        return;
    }
    i -= N8_X;
    if (i < N8_WQ) {
        cvt8(wq + i * 8, g_wqh + i * 8, qscale);
        return;
    }
    i -= N8_WQ;
    if (i < N8_WO) {
        cvt8(wo + i * 8, g_woh + i * 8, 1.0f);
        return;
    }
    i -= N8_WO;
    if (i < N8_WK) {
        long r = i >> 6;
        int  c = (int)(i & 63) * 8;
        cvt8(wk + r * (KVHH * HDD) + c, g_wkv + r * KVSTR + c, 1.0f);
        return;
    }
    i -= N8_WK;
    {
        long r = i >> 6;
        int  c = (int)(i & 63) * 8;
        cvt8(wv + r * (KVHH * HDD) + c, g_wkv + r * KVSTR + KVHH * HDD + c, 1.0f);
    }
}

// ===================== fp16 cp.async GEMM, 128x256 tile =====================
#define ASTRH 40
#define BSTRH 264
#define STG_A (128 * ASTRH * 2)
#define STG_B (32 * BSTRH * 2)
#define STG   (STG_A + STG_B)
#define NSTAGE 4
#define GSMEM (NSTAGE * STG)

template <bool QKV, bool HOUT>
__global__ __launch_bounds__(256, 1) void gemm_hp(
    const __half* __restrict__ A, const __half* __restrict__ B0,
    void* __restrict__ C0, int M, int N0, int K)
{
    extern __shared__ __half shh[];
    const uint32_t sbase = smem_u32(shh);

    const int tid  = threadIdx.x;
    const int lane = tid & 31;
    const int warp = tid >> 5;
    const int warpM = warp & 1;
    const int warpN = warp >> 1;
    const int g = lane >> 2;
    const int t = lane & 3;
    const int m0 = blockIdx.y * 128;

    const __half* Bm;
    __half* Ch = 0;
    float*  Cf = 0;
    int N, nb;
    if (QKV) {
        int n0 = blockIdx.x * 256;
        bool isq = n0 < DD;
        if (isq) {
            Bm = B0; Ch = (__half*)C0; N = DD; nb = n0;
        } else {
            Bm = g_wkv; Ch = g_kvh; N = KVSTR; nb = n0 - DD;
        }
    } else {
        Bm = B0; N = N0; nb = blockIdx.x * 256;
        if (HOUT) Ch = (__half*)C0; else Cf = (float*)C0;
    }

    const int lrow8 = ((lane >> 3) & 1) * 8 + (lane & 7);
    const int lcol8 = (lane >> 4) * 8;

    float acc[4][8][4] = {};
    const int NS = K >> 5;

    auto issue = [&](int s) {
        const int p = s & (NSTAGE - 1);
        const uint32_t ab = sbase + p * STG;
        const uint32_t bb = ab + STG_A;
        const int k0 = s << 5;
        {
            int r = tid >> 2, kg = tid & 3;
            CP_ASYNC16(ab + (uint32_t)((r * ASTRH + kg * 8) * 2),
                       &A[(long)(m0 + r) * K + k0 + kg * 8]);
            r += 64;
            CP_ASYNC16(ab + (uint32_t)((r * ASTRH + kg * 8) * 2),
                       &A[(long)(m0 + r) * K + k0 + kg * 8]);
        }
        {
            int r0 = tid >> 5, nc = tid & 31;
            #pragma unroll
            for (int j = 0; j < 4; j++) {
                int r = r0 + j * 8;
                CP_ASYNC16(bb + (uint32_t)((r * BSTRH + nc * 8) * 2),
                           &Bm[(long)(k0 + r) * N + nb + nc * 8]);
            }
        }
    };

    issue(0); CP_COMMIT();
    issue(1); CP_COMMIT();
    issue(2); CP_COMMIT();

    for (int s = 0; s < NS; s++) {
        CP_WAIT2();
        __syncthreads();

        if (s + 3 < NS) issue(s + 3);
        CP_COMMIT();

        const int p = s & (NSTAGE - 1);
        const uint32_t ab = sbase + p * STG;
        const uint32_t bb = ab + STG_A;

        #pragma unroll
        for (int ks = 0; ks < 2; ks++) {
            uint32_t afr[4][4];
            #pragma unroll
            for (int mi = 0; mi < 4; mi++) {
                int row = warpM * 64 + mi * 16 + lrow8;
                int col = ks * 16 + lcol8;
                ldsm_x4(afr[mi], ab + (uint32_t)((row * ASTRH + col) * 2));
            }
            uint32_t bfr[8][2];
            #pragma unroll
            for (int ni2 = 0; ni2 < 4; ni2++) {
                int krow = ks * 16 + lrow8;
                int col  = warpN * 64 + ni2 * 16 + lcol8;
                uint32_t r4[4];
                ldsm_x4_t(r4, bb + (uint32_t)((krow * BSTRH + col) * 2));
                bfr[ni2 * 2][0] = r4[0]; bfr[ni2 * 2][1] = r4[1];
                bfr[ni2 * 2 + 1][0] = r4[2]; bfr[ni2 * 2 + 1][1] = r4[3];
            }
            #pragma unroll
            for (int mi = 0; mi < 4; mi++)
                #pragma unroll
                for (int ni = 0; ni < 8; ni++)
                    mma_f16(acc[mi][ni], afr[mi], bfr[ni][0], bfr[ni][1]);
        }
    }

    #pragma unroll
    for (int mi = 0; mi < 4; mi++) {
        int r0 = m0 + warpM * 64 + mi * 16 + g;
        #pragma unroll
        for (int ni = 0; ni < 8; ni++) {
            int c0 = nb + warpN * 64 + ni * 8 + t * 2;
            if (QKV || HOUT) {
                *(uint32_t*)&Ch[(long)r0 * N + c0] =
                    pack_h2(acc[mi][ni][0], acc[mi][ni][1]);
                *(uint32_t*)&Ch[(long)(r0 + 8) * N + c0] =
                    pack_h2(acc[mi][ni][2], acc[mi][ni][3]);
            } else {
                *(float2*)&Cf[(long)r0 * N + c0] =
                    make_float2(acc[mi][ni][0], acc[mi][ni][1]);
                *(float2*)&Cf[(long)(r0 + 8) * N + c0] =
                    make_float2(acc[mi][ni][2], acc[mi][ni][3]);
            }
        }
    }
}

// ================= RoPE on half q and k, 8 cols/thread ======================
__global__ void rope_h_kernel(const float* __restrict__ cosp,
                              const float* __restrict__ sinp)
{
    long idx = (long)blockIdx.x * blockDim.x + threadIdx.x;
    const long total = (long)BB * SS * (HH + KVHH) * 8;
    if (idx >= total) return;
    int d = (int)(idx & 7) * 8;
    long row = idx >> 3;
    int head = (int)(row % (HH + KVHH));
    long bs = row / (HH + KVHH);

    float4 c0 = *(const float4*)&cosp[bs * HDD + d];
    float4 c1 = *(const float4*)&cosp[bs * HDD + d + 4];
    float4 s0 = *(const float4*)&sinp[bs * HDD + d];
    float4 s1 = *(const float4*)&sinp[bs * HDD + d + 4];

    __half* ptr;
    if (head < HH)
        ptr = g_qh + bs * (HH * HDD) + head * HDD;
    else
        ptr = g_kvh + bs * KVSTR + (head - HH) * HDD;

    uint4 lo4 = *(uint4*)&ptr[d];
    uint4 hi4 = *(uint4*)&ptr[d + 64];
    __half* lo = (__half*)&lo4;
    __half* hi = (__half*)&hi4;
    float cs[8] = {c0.x, c0.y, c0.z, c0.w, c1.x, c1.y, c1.z, c1.w};
    float sn[8] = {s0.x, s0.y, s0.z, s0.w, s1.x, s1.y, s1.z, s1.w};
    uint4 olo, ohi;
    __half* plo = (__half*)&olo;
    __half* phi = (__half*)&ohi;
    #pragma unroll
    for (int j = 0; j < 8; j++) {
        float a = __half2float(lo[j]);
        float b = __half2float(hi[j]);
        plo[j] = __float2half_rn(a * cs[j] - b * sn[j]);
        phi[j] = __float2half_rn(b * cs[j] + a * sn[j]);
    }
    *(uint4*)&ptr[d]      = olo;
    *(uint4*)&ptr[d + 64] = ohi;
}

// ============ Flash attention (fp16 mma, BN=64, 2 CTAs/SM) ==================
#define FA_BM 128
#define FA_BN 64
#define FA_STRH 136
#define FA_TILE (FA_BN * FA_STRH)          // 8704 halves per K or V tile
#define FA_STGH (2 * FA_TILE)              // 17408 halves per stage (K+V)
#define FA_SMEMB (2 * FA_STGH * 2 + FA_BM * FA_STRH * 2)   // 104448 B

__global__ __launch_bounds__(256, 2) void flash_attn_hp()
{
    extern __shared__ __half shh[];
    const uint32_t s0 = smem_u32(shh);
    __half* Qs = shh + 2 * FA_STGH;
    const uint32_t q0 = s0 + (uint32_t)(2 * FA_STGH * 2);

    const int qb  = (int)gridDim.x - 1 - (int)blockIdx.x;  // longest first
    const int h   = blockIdx.y;
    const int b   = blockIdx.z;
    const int kvh = h / NREP;
    const int tid  = threadIdx.x;
    const int lane = tid & 31;
    const int warp = tid >> 5;
    const int g = lane >> 2;
    const int t = lane & 3;
    const int woff = warp * 16;
    const unsigned FMASK = 0xffffffffu;
    const int lrow8 = ((lane >> 3) & 1) * 8 + (lane & 7);
    const int lcol8 = (lane >> 4) * 8;

    const int ntiles = 2 * qb + 2;
    const __half* kb0 = g_kvh + (long)b * SS * KVSTR + kvh * HDD;
    const __half* vb0 = kb0 + KVHH * HDD;

    // per-thread cp.async mapping: 64 rows x 16 chunks = 1024 chunks / 256 thr
    const int cr = tid >> 4;          // base row 0..15 (+16,+32,+48)
    const int cc = (tid & 15) * 8;

    auto issue_tile = [&](int kt, int buf) {
        const uint32_t kb = s0 + (uint32_t)(buf * FA_STGH * 2);
        const uint32_t vb = kb + (uint32_t)(FA_TILE * 2);
        #pragma unroll
        for (int j = 0; j < 4; j++) {
            int r = cr + j * 16;
            long grow = (long)(kt * FA_BN + r);
            CP_ASYNC16(kb + (uint32_t)((r * FA_STRH + cc) * 2),
                       &kb0[grow * KVSTR + cc]);
            CP_ASYNC16(vb + (uint32_t)((r * FA_STRH + cc) * 2),
                       &vb0[grow * KVSTR + cc]);
        }
    };

    issue_tile(0, 0); CP_COMMIT();

    const __half* qbase = g_qh + ((long)b * SS + (long)qb * FA_BM) * (HH * HDD) + h * HDD;
    for (int i = tid; i < FA_BM * 16; i += 256) {
        int r = i >> 4, c = (i & 15) * 8;
        *(uint4*)&Qs[r * FA_STRH + c] = *(const uint4*)&qbase[(long)r * (HH * HDD) + c];
    }
    __syncthreads();

    float o[16][4] = {};
    float m_g = -1e30f, m_g8 = -1e30f, l_g = 0.0f, l_g8 = 0.0f;
    const int rg  = qb * FA_BM + woff + g;
    const int rg8 = rg + 8;

    int buf = 0;
    for (int kt = 0; kt < ntiles; kt++) {
        CP_WAIT0();
        __syncthreads();

        if (kt + 1 < ntiles) issue_tile(kt + 1, buf ^ 1);
        CP_COMMIT();

        const uint32_t ksb = s0 + (uint32_t)(buf * FA_STGH * 2);
        const uint32_t vsb = ksb + (uint32_t)(FA_TILE * 2);

        // ---- scores (log2 domain); ks-outer keeps qa liveness at 4 regs ----
        float s[8][4] = {};
        #pragma unroll
        for (int ks = 0; ks < 8; ks++) {
            uint32_t qa[4];
            ldsm_x4(qa, q0 + (uint32_t)(((woff + lrow8) * FA_STRH
                                         + ks * 16 + lcol8) * 2));
            #pragma unroll
            for (int npair = 0; npair < 4; npair++) {
                uint32_t r4[4];
                ldsm_x4(r4, ksb + (uint32_t)(((npair * 16 + lrow8) * FA_STRH
                                              + ks * 16 + lcol8) * 2));
                mma_f16(s[npair * 2],     qa, r4[0], r4[2]);
                mma_f16(s[npair * 2 + 1], qa, r4[1], r4[3]);
            }
        }

        // ---- causal mask (tiles straddling the diagonal) ----
        if (kt * FA_BN + FA_BN - 1 > qb * FA_BM + woff) {
            #pragma unroll
            for (int n = 0; n < 8; n++) {
                int c0 = kt * FA_BN + n * 8 + 2 * t;
                int c1 = c0 + 1;
                if (c0 > rg)  s[n][0] = -1e30f;
                if (c1 > rg)  s[n][1] = -1e30f;
                if (c0 > rg8) s[n][2] = -1e30f;
                if (c1 > rg8) s[n][3] = -1e30f;
            }
        }

        // ---- max reduction ----
        float tm_g = -1e30f, tm_g8 = -1e30f;
        #pragma unroll
        for (int n = 0; n < 8; n++) {
            tm_g  = fmaxf(tm_g,  fmaxf(s[n][0], s[n][1]));
            tm_g8 = fmaxf(tm_g8, fmaxf(s[n][2], s[n][3]));
        }
        tm_g  = fmaxf(tm_g,  __shfl_xor_sync(FMASK, tm_g, 1));
        tm_g  = fmaxf(tm_g,  __shfl_xor_sync(FMASK, tm_g, 2));
        tm_g8 = fmaxf(tm_g8, __shfl_xor_sync(FMASK, tm_g8, 1));
        tm_g8 = fmaxf(tm_g8, __shfl_xor_sync(FMASK, tm_g8, 2));

        float mn_g  = fmaxf(m_g, tm_g);
        float mn_g8 = fmaxf(m_g8, tm_g8);
        float corr_g  = exp2f(m_g - mn_g);
        float corr_g8 = exp2f(m_g8 - mn_g8);
        m_g = mn_g; m_g8 = mn_g8;

        // ---- exp, sum, pack P early (s dies here) ----
        float sum_g = 0.0f, sum_g8 = 0.0f;
        uint32_t p[8][2];
        #pragma unroll
        for (int n = 0; n < 8; n++) {
            float e0 = exp2f(s[n][0] - m_g);
            float e1 = exp2f(s[n][1] - m_g);
            float e2 = exp2f(s[n][2] - m_g8);
            float e3 = exp2f(s[n][3] - m_g8);
            sum_g  += e0 + e1;
            sum_g8 += e2 + e3;
            p[n][0] = pack_h2(e0, e1);
            p[n][1] = pack_h2(e2, e3);
        }
        sum_g  += __shfl_xor_sync(FMASK, sum_g, 1);
        sum_g  += __shfl_xor_sync(FMASK, sum_g, 2);
        sum_g8 += __shfl_xor_sync(FMASK, sum_g8, 1);
        sum_g8 += __shfl_xor_sync(FMASK, sum_g8, 2);
        l_g  = l_g  * corr_g  + sum_g;
        l_g8 = l_g8 * corr_g8 + sum_g8;

        #pragma unroll
        for (int nn = 0; nn < 16; nn++) {
            o[nn][0] *= corr_g;  o[nn][1] *= corr_g;
            o[nn][2] *= corr_g8; o[nn][3] *= corr_g8;
        }

        // ---- PV over 64 kv rows ----
        #pragma unroll
        for (int jj = 0; jj < 2; jj++) {
            uint32_t pa0[4] = {p[4 * jj][0],     p[4 * jj][1],
                               p[4 * jj + 1][0], p[4 * jj + 1][1]};
            uint32_t pa1[4] = {p[4 * jj + 2][0], p[4 * jj + 2][1],
                               p[4 * jj + 3][0], p[4 * jj + 3][1]};
            int krow = jj * 32 + (lane >> 3) * 8 + (lane & 7);
            #pragma unroll
            for (int nn = 0; nn < 16; nn++) {
                uint32_t r4[4];
                ldsm_x4_t(r4, vsb + (uint32_t)((krow * FA_STRH + nn * 8) * 2));
                mma_f16(o[nn], pa0, r4[0], r4[1]);
                mma_f16(o[nn], pa1, r4[2], r4[3]);
            }
        }

        __syncthreads();
        buf ^= 1;
    }

    float il_g = 1.0f / l_g, il_g8 = 1.0f / l_g8;
    long orow = (long)b * SS + qb * FA_BM + woff + g;
    __half* obase = g_ah + orow * (HH * HDD) + h * HDD;
    #pragma unroll
    for (int nn = 0; nn < 16; nn++) {
        int col = nn * 8 + 2 * t;
        *(uint32_t*)&obase[col] = pack_h2(o[nn][0] * il_g, o[nn][1] * il_g);
        *(uint32_t*)&obase[(long)8 * (HH * HDD) + col] =
            pack_h2(o[nn][2] * il_g8, o[nn][3] * il_g8);
    }
}

// ================= launcher =================================================
extern "C" void kernel_launch(void* const* d_in, const int* in_sizes, int n_in,
                              void* d_out, int out_size)
{
    const float* x    = (const float*)d_in[0];
    const float* cosp = (const float*)d_in[1];
    const float* sinp = (const float*)d_in[2];
    const float* wq   = (const float*)d_in[3];
    const float* wk   = (const float*)d_in[4];
    const float* wv   = (const float*)d_in[5];
    const float* wo   = (const float*)d_in[6];
    float* out = (float*)d_out;

    __half *pxh, *pwqh, *pwoh, *pqh, *pah;
    cudaGetSymbolAddress((void**)&pxh,  g_xh);
    cudaGetSymbolAddress((void**)&pwqh, g_wqh);
    cudaGetSymbolAddress((void**)&pwoh, g_woh);
    cudaGetSymbolAddress((void**)&pqh,  g_qh);
    cudaGetSymbolAddress((void**)&pah,  g_ah);

    const int M = BB * SS;  // 8192
    // 1/sqrt(128) * log2(e): scores arrive in log2 domain
    const float scale = 0.08838834764831845f * 1.4426950408889634f;

    {
        unsigned blks = (unsigned)((N8_TOT + 255) / 256);
        cvt_all_kernel<<<blks, 256>>>(x, wq, wo, wk, wv, scale);
    }

    cudaFuncSetAttribute(gemm_hp<true, true>,
                         cudaFuncAttributeMaxDynamicSharedMemorySize, GSMEM);
    cudaFuncSetAttribute(gemm_hp<false, false>,
                         cudaFuncAttributeMaxDynamicSharedMemorySize, GSMEM);

    gemm_hp<true, true><<<dim3((DD + KVSTR) / 256, M / 128), 256, GSMEM>>>(
        pxh, pwqh, pqh, M, DD, DD);

    {
        long total = (long)BB * SS * (HH + KVHH) * 8;
        int blocks = (int)((total + 255) / 256);
        rope_h_kernel<<<blocks, 256>>>(cosp, sinp);
    }

    {
        cudaFuncSetAttribute(flash_attn_hp, cudaFuncAttributeMaxDynamicSharedMemorySize,
                             FA_SMEMB);
        flash_attn_hp<<<dim3(SS / FA_BM, HH, BB), 256, FA_SMEMB>>>();
    }

    gemm_hp<false, false><<<dim3(DD / 256, M / 128), 256, GSMEM>>>(
        pah, pwoh, out, M, DD, DD);
}

// round 16
// speedup vs baseline: 1.1474x; 1.1474x over previous
#include <cuda_runtime.h>
#include <cuda_fp16.h>
#include <cstdint>
#include <math.h>

#define BB   2
#define SS   4096
#define DD   2048
#define HH   16
#define KVHH 4
#define HDD  128
#define NREP 4
#define KVSTR (2 * KVHH * HDD)   // 1024 halves: combined k|v row

// -------- scratch (device globals; no allocation allowed) --------
__device__ __half g_xh[(long)BB * SS * DD];
__device__ __half g_wqh[(long)DD * DD];
__device__ __half g_wkv[(long)DD * KVSTR];
__device__ __half g_woh[(long)DD * DD];
__device__ __half g_qh[(long)BB * SS * HH * HDD];
__device__ __half g_kvh[(long)BB * SS * KVSTR];
__device__ __half g_ah[(long)BB * SS * HH * HDD];

// ===================== helpers ==============================================
__device__ __forceinline__ uint32_t smem_u32(const void* p) {
    uint32_t a;
    asm("{ .reg .u64 t; cvta.to.shared.u64 t, %1; cvt.u32.u64 %0, t; }"
        : "=r"(a) : "l"(p));
    return a;
}
__device__ __forceinline__ void ldsm_x4(uint32_t r[4], uint32_t addr) {
    asm volatile("ldmatrix.sync.aligned.m8n8.x4.shared.b16 {%0,%1,%2,%3}, [%4];"
        : "=r"(r[0]), "=r"(r[1]), "=r"(r[2]), "=r"(r[3]) : "r"(addr));
}
__device__ __forceinline__ void ldsm_x4_t(uint32_t r[4], uint32_t addr) {
    asm volatile("ldmatrix.sync.aligned.m8n8.x4.trans.shared.b16 {%0,%1,%2,%3}, [%4];"
        : "=r"(r[0]), "=r"(r[1]), "=r"(r[2]), "=r"(r[3]) : "r"(addr));
}
__device__ __forceinline__ void mma_f16(float c[4], const uint32_t a[4],
                                        const uint32_t b0, const uint32_t b1) {
    asm volatile(
        "mma.sync.aligned.m16n8k16.row.col.f32.f16.f16.f32 "
        "{%0,%1,%2,%3}, {%4,%5,%6,%7}, {%8,%9}, {%0,%1,%2,%3};"
        : "+f"(c[0]), "+f"(c[1]), "+f"(c[2]), "+f"(c[3])
        : "r"(a[0]), "r"(a[1]), "r"(a[2]), "r"(a[3]), "r"(b0), "r"(b1));
}
__device__ __forceinline__ uint32_t pack_h2(float lo, float hi) {
    __half2 h = __floats2half2_rn(lo, hi);
    return *(uint32_t*)&h;
}

#define CP_ASYNC16(saddr, gptr) \
    asm volatile("cp.async.cg.shared.global [%0], [%1], 16;" \
                 :: "r"(saddr), "l"(gptr))
#define CP_COMMIT() asm volatile("cp.async.commit_group;" ::: "memory")
#define CP_WAIT0()  asm volatile("cp.async.wait_group 0;" ::: "memory")
#define CP_WAIT2()  asm volatile("cp.async.wait_group 2;" ::: "memory")

// ===================== fused float->half conversion =========================
#define N8_X  ((long)BB * SS * DD / 8)
#define N8_WQ ((long)DD * DD / 8)
#define N8_WO ((long)DD * DD / 8)
#define N8_WK ((long)DD * (KVHH * HDD) / 8)
#define N8_TOT (N8_X + N8_WQ + N8_WO + 2 * N8_WK)

__device__ __forceinline__ void cvt8(const float* in, __half* out, float s) {
    const float4* p = (const float4*)in;
    float4 v0 = p[0], v1 = p[1];
    __half h[8];
    h[0] = __float2half_rn(v0.x * s); h[1] = __float2half_rn(v0.y * s);
    h[2] = __float2half_rn(v0.z * s); h[3] = __float2half_rn(v0.w * s);
    h[4] = __float2half_rn(v1.x * s); h[5] = __float2half_rn(v1.y * s);
    h[6] = __float2half_rn(v1.z * s); h[7] = __float2half_rn(v1.w * s);
    *(uint4*)out = *(uint4*)h;
}

__global__ void cvt_all_kernel(const float* __restrict__ x,
                               const float* __restrict__ wq,
                               const float* __restrict__ wo,
                               const float* __restrict__ wk,
                               const float* __restrict__ wv,
                               float qscale)
{
    long i = (long)blockIdx.x * blockDim.x + threadIdx.x;
    if (i >= N8_TOT) return;
    if (i < N8_X) {
        cvt8(x + i * 8, g_xh + i * 8, 1.0f);
        return;
    }
    i -= N8_X;
    if (i < N8_WQ) {
        cvt8(wq + i * 8, g_wqh + i * 8, qscale);
        return;
    }
    i -= N8_WQ;
    if (i < N8_WO) {
        cvt8(wo + i * 8, g_woh + i * 8, 1.0f);
        return;
    }
    i -= N8_WO;
    if (i < N8_WK) {
        long r = i >> 6;
        int  c = (int)(i & 63) * 8;
        cvt8(wk + r * (KVHH * HDD) + c, g_wkv + r * KVSTR + c, 1.0f);
        return;
    }
    i -= N8_WK;
    {
        long r = i >> 6;
        int  c = (int)(i & 63) * 8;
        cvt8(wv + r * (KVHH * HDD) + c, g_wkv + r * KVSTR + KVHH * HDD + c, 1.0f);
    }
}

// ============ fp16 cp.async GEMM, 128x128 tile, 2 CTAs/SM ===================
#define ASTRH 40
#define BSTRH 136
#define STG_A (128 * ASTRH * 2)   // 10240 B
#define STG_B (32 * BSTRH * 2)    // 8704 B
#define STG   (STG_A + STG_B)     // 18944 B
#define NSTAGE 4
#define GSMEM (NSTAGE * STG)      // 75776 B

template <bool QKV, bool HOUT>
__global__ __launch_bounds__(256, 2) void gemm_hp(
    const __half* __restrict__ A, const __half* __restrict__ B0,
    void* __restrict__ C0, int M, int N0, int K)
{
    extern __shared__ __half shh[];
    const uint32_t sbase = smem_u32(shh);

    const int tid  = threadIdx.x;
    const int lane = tid & 31;
    const int warp = tid >> 5;
    const int warpM = warp & 1;        // x64 rows
    const int warpN = warp >> 1;       // x32 cols
    const int g = lane >> 2;
    const int t = lane & 3;
    const int m0 = blockIdx.y * 128;

    const __half* Bm;
    __half* Ch = 0;
    float*  Cf = 0;
    int N, nb;
    if (QKV) {
        int n0 = blockIdx.x * 128;
        if (n0 < DD) {
            Bm = B0; Ch = (__half*)C0; N = DD; nb = n0;
        } else {
            Bm = g_wkv; Ch = g_kvh; N = KVSTR; nb = n0 - DD;
        }
    } else {
        Bm = B0; N = N0; nb = blockIdx.x * 128;
        if (HOUT) Ch = (__half*)C0; else Cf = (float*)C0;
    }

    const int lrow8 = ((lane >> 3) & 1) * 8 + (lane & 7);
    const int lcol8 = (lane >> 4) * 8;

    float acc[4][4][4] = {};
    const int NS = K >> 5;

    auto issue = [&](int s) {
        const int p = s & (NSTAGE - 1);
        const uint32_t ab = sbase + p * STG;
        const uint32_t bb = ab + STG_A;
        const int k0 = s << 5;
        // A: 2 chunks (rows tid>>2 and +64)
        {
            int r = tid >> 2, kg = tid & 3;
            CP_ASYNC16(ab + (uint32_t)((r * ASTRH + kg * 8) * 2),
                       &A[(long)(m0 + r) * K + k0 + kg * 8]);
            r += 64;
            CP_ASYNC16(ab + (uint32_t)((r * ASTRH + kg * 8) * 2),
                       &A[(long)(m0 + r) * K + k0 + kg * 8]);
        }
        // B: 2 chunks (rows tid>>4 and +16), 16 chunks/row
        {
            int r = tid >> 4, nc = tid & 15;
            CP_ASYNC16(bb + (uint32_t)((r * BSTRH + nc * 8) * 2),
                       &Bm[(long)(k0 + r) * N + nb + nc * 8]);
            r += 16;
            CP_ASYNC16(bb + (uint32_t)((r * BSTRH + nc * 8) * 2),
                       &Bm[(long)(k0 + r) * N + nb + nc * 8]);
        }
    };

    issue(0); CP_COMMIT();
    issue(1); CP_COMMIT();
    issue(2); CP_COMMIT();

    for (int s = 0; s < NS; s++) {
        CP_WAIT2();
        __syncthreads();

        if (s + 3 < NS) issue(s + 3);
        CP_COMMIT();

        const int p = s & (NSTAGE - 1);
        const uint32_t ab = sbase + p * STG;
        const uint32_t bb = ab + STG_A;

        #pragma unroll
        for (int ks = 0; ks < 2; ks++) {
            uint32_t afr[4][4];
            #pragma unroll
            for (int mi = 0; mi < 4; mi++) {
                int row = warpM * 64 + mi * 16 + lrow8;
                int col = ks * 16 + lcol8;
                ldsm_x4(afr[mi], ab + (uint32_t)((row * ASTRH + col) * 2));
            }
            uint32_t bfr[4][2];
            #pragma unroll
            for (int ni2 = 0; ni2 < 2; ni2++) {
                int krow = ks * 16 + lrow8;
                int col  = warpN * 32 + ni2 * 16 + lcol8;
                uint32_t r4[4];
                ldsm_x4_t(r4, bb + (uint32_t)((krow * BSTRH + col) * 2));
                bfr[ni2 * 2][0] = r4[0]; bfr[ni2 * 2][1] = r4[1];
                bfr[ni2 * 2 + 1][0] = r4[2]; bfr[ni2 * 2 + 1][1] = r4[3];
            }
            #pragma unroll
            for (int mi = 0; mi < 4; mi++)
                #pragma unroll
                for (int ni = 0; ni < 4; ni++)
                    mma_f16(acc[mi][ni], afr[mi], bfr[ni][0], bfr[ni][1]);
        }
    }

    #pragma unroll
    for (int mi = 0; mi < 4; mi++) {
        int r0 = m0 + warpM * 64 + mi * 16 + g;
        #pragma unroll
        for (int ni = 0; ni < 4; ni++) {
            int c0 = nb + warpN * 32 + ni * 8 + t * 2;
            if (QKV || HOUT) {
                *(uint32_t*)&Ch[(long)r0 * N + c0] =
                    pack_h2(acc[mi][ni][0], acc[mi][ni][1]);
                *(uint32_t*)&Ch[(long)(r0 + 8) * N + c0] =
                    pack_h2(acc[mi][ni][2], acc[mi][ni][3]);
            } else {
                *(float2*)&Cf[(long)r0 * N + c0] =
                    make_float2(acc[mi][ni][0], acc[mi][ni][1]);
                *(float2*)&Cf[(long)(r0 + 8) * N + c0] =
                    make_float2(acc[mi][ni][2], acc[mi][ni][3]);
            }
        }
    }
}

// ================= RoPE on half q and k, 8 cols/thread ======================
__global__ void rope_h_kernel(const float* __restrict__ cosp,
                              const float* __restrict__ sinp)
{
    long idx = (long)blockIdx.x * blockDim.x + threadIdx.x;
    const long total = (long)BB * SS * (HH + KVHH) * 8;
    if (idx >= total) return;
    int d = (int)(idx & 7) * 8;
    long row = idx >> 3;
    int head = (int)(row % (HH + KVHH));
    long bs = row / (HH + KVHH);

    float4 c0 = *(const float4*)&cosp[bs * HDD + d];
    float4 c1 = *(const float4*)&cosp[bs * HDD + d + 4];
    float4 s0 = *(const float4*)&sinp[bs * HDD + d];
    float4 s1 = *(const float4*)&sinp[bs * HDD + d + 4];

    __half* ptr;
    if (head < HH)
        ptr = g_qh + bs * (HH * HDD) + head * HDD;
    else
        ptr = g_kvh + bs * KVSTR + (head - HH) * HDD;

    uint4 lo4 = *(uint4*)&ptr[d];
    uint4 hi4 = *(uint4*)&ptr[d + 64];
    __half* lo = (__half*)&lo4;
    __half* hi = (__half*)&hi4;
    float cs[8] = {c0.x, c0.y, c0.z, c0.w, c1.x, c1.y, c1.z, c1.w};
    float sn[8] = {s0.x, s0.y, s0.z, s0.w, s1.x, s1.y, s1.z, s1.w};
    uint4 olo, ohi;
    __half* plo = (__half*)&olo;
    __half* phi = (__half*)&ohi;
    #pragma unroll
    for (int j = 0; j < 8; j++) {
        float a = __half2float(lo[j]);
        float b = __half2float(hi[j]);
        plo[j] = __float2half_rn(a * cs[j] - b * sn[j]);
        phi[j] = __float2half_rn(b * cs[j] + a * sn[j]);
    }
    *(uint4*)&ptr[d]      = olo;
    *(uint4*)&ptr[d + 64] = ohi;
}

// ================= Flash attention (fp16 mma, BN=128, 2-stage) ==============
#define FA_BM 128
#define FA_BN 128
#define FA_STRH 136
#define FA_TILE (FA_BN * FA_STRH)
#define FA_STGH (2 * FA_TILE)
#define FA_SMEMB (2 * FA_STGH * 2 + FA_BM * FA_STRH * 2)   // 174080 B

__global__ __launch_bounds__(256, 1) void flash_attn_hp()
{
    extern __shared__ __half shh[];
    const uint32_t s0 = smem_u32(shh);
    __half* Qs = shh + 2 * FA_STGH;
    const uint32_t q0 = s0 + (uint32_t)(2 * FA_STGH * 2);

    const int qb  = (int)gridDim.x - 1 - (int)blockIdx.x;
    const int h   = blockIdx.y;
    const int b   = blockIdx.z;
    const int kvh = h / NREP;
    const int tid  = threadIdx.x;
    const int lane = tid & 31;
    const int warp = tid >> 5;
    const int g = lane >> 2;
    const int t = lane & 3;
    const int woff = warp * 16;
    const unsigned FMASK = 0xffffffffu;
    const int lrow8 = ((lane >> 3) & 1) * 8 + (lane & 7);
    const int lcol8 = (lane >> 4) * 8;

    const int ntiles = qb + 1;
    const __half* kb0 = g_kvh + (long)b * SS * KVSTR + kvh * HDD;
    const __half* vb0 = kb0 + KVHH * HDD;

    const int cr = tid >> 4;
    const int cc = (tid & 15) * 8;

    auto issue_tile = [&](int kt, int buf) {
        const uint32_t kb = s0 + (uint32_t)(buf * FA_STGH * 2);
        const uint32_t vb = kb + (uint32_t)(FA_TILE * 2);
        #pragma unroll
        for (int j = 0; j < 8; j++) {
            int r = cr + j * 16;
            long grow = (long)(kt * FA_BN + r);
            CP_ASYNC16(kb + (uint32_t)((r * FA_STRH + cc) * 2),
                       &kb0[grow * KVSTR + cc]);
            CP_ASYNC16(vb + (uint32_t)((r * FA_STRH + cc) * 2),
                       &vb0[grow * KVSTR + cc]);
        }
    };

    issue_tile(0, 0); CP_COMMIT();

    const __half* qbase = g_qh + ((long)b * SS + (long)qb * FA_BM) * (HH * HDD) + h * HDD;
    for (int i = tid; i < FA_BM * 16; i += 256) {
        int r = i >> 4, c = (i & 15) * 8;
        *(uint4*)&Qs[r * FA_STRH + c] = *(const uint4*)&qbase[(long)r * (HH * HDD) + c];
    }
    __syncthreads();

    float o[16][4] = {};
    float m_g = -1e30f, m_g8 = -1e30f, l_g = 0.0f, l_g8 = 0.0f;
    const int rg  = qb * FA_BM + woff + g;
    const int rg8 = rg + 8;

    int buf = 0;
    for (int kt = 0; kt < ntiles; kt++) {
        CP_WAIT0();
        __syncthreads();

        if (kt + 1 < ntiles) issue_tile(kt + 1, buf ^ 1);
        CP_COMMIT();

        const uint32_t ksb = s0 + (uint32_t)(buf * FA_STGH * 2);
        const uint32_t vsb = ksb + (uint32_t)(FA_TILE * 2);

        // ---- scores (log2 domain; Q fragments reloaded per tile) ----
        float s[16][4] = {};
        {
            uint32_t qa[8][4];
            #pragma unroll
            for (int ks = 0; ks < 8; ks++) {
                int row = woff + lrow8;
                int col = ks * 16 + lcol8;
                ldsm_x4(qa[ks], q0 + (uint32_t)((row * FA_STRH + col) * 2));
            }
            #pragma unroll
            for (int npair = 0; npair < 8; npair++) {
                #pragma unroll
                for (int ks = 0; ks < 8; ks++) {
                    uint32_t r4[4];
                    ldsm_x4(r4, ksb + (uint32_t)(((npair * 16 + lrow8) * FA_STRH
                                                  + ks * 16 + lcol8) * 2));
                    mma_f16(s[npair * 2],     qa[ks], r4[0], r4[2]);
                    mma_f16(s[npair * 2 + 1], qa[ks], r4[1], r4[3]);
                }
            }
        }

        if (kt == qb) {
            #pragma unroll
            for (int n = 0; n < 16; n++) {
                int c0 = kt * FA_BN + n * 8 + 2 * t;
                int c1 = c0 + 1;
                if (c0 > rg)  s[n][0] = -1e30f;
                if (c1 > rg)  s[n][1] = -1e30f;
                if (c0 > rg8) s[n][2] = -1e30f;
                if (c1 > rg8) s[n][3] = -1e30f;
            }
        }

        float tm_g = -1e30f, tm_g8 = -1e30f;
        #pragma unroll
        for (int n = 0; n < 16; n++) {
            tm_g  = fmaxf(tm_g,  fmaxf(s[n][0], s[n][1]));
            tm_g8 = fmaxf(tm_g8, fmaxf(s[n][2], s[n][3]));
        }
        tm_g  = fmaxf(tm_g,  __shfl_xor_sync(FMASK, tm_g, 1));
        tm_g  = fmaxf(tm_g,  __shfl_xor_sync(FMASK, tm_g, 2));
        tm_g8 = fmaxf(tm_g8, __shfl_xor_sync(FMASK, tm_g8, 1));
        tm_g8 = fmaxf(tm_g8, __shfl_xor_sync(FMASK, tm_g8, 2));

        float mn_g  = fmaxf(m_g, tm_g);
        float mn_g8 = fmaxf(m_g8, tm_g8);
        float corr_g  = exp2f(m_g - mn_g);
        float corr_g8 = exp2f(m_g8 - mn_g8);
        m_g = mn_g; m_g8 = mn_g8;

        float sum_g = 0.0f, sum_g8 = 0.0f;
        uint32_t p[16][2];
        #pragma unroll
        for (int n = 0; n < 16; n++) {
            float e0 = exp2f(s[n][0] - m_g);
            float e1 = exp2f(s[n][1] - m_g);
            float e2 = exp2f(s[n][2] - m_g8);
            float e3 = exp2f(s[n][3] - m_g8);
            sum_g  += e0 + e1;
            sum_g8 += e2 + e3;
            p[n][0] = pack_h2(e0, e1);
            p[n][1] = pack_h2(e2, e3);
        }
        sum_g  += __shfl_xor_sync(FMASK, sum_g, 1);
        sum_g  += __shfl_xor_sync(FMASK, sum_g, 2);
        sum_g8 += __shfl_xor_sync(FMASK, sum_g8, 1);
        sum_g8 += __shfl_xor_sync(FMASK, sum_g8, 2);
        l_g  = l_g  * corr_g  + sum_g;
        l_g8 = l_g8 * corr_g8 + sum_g8;

        #pragma unroll
        for (int nn = 0; nn < 16; nn++) {
            o[nn][0] *= corr_g;  o[nn][1] *= corr_g;
            o[nn][2] *= corr_g8; o[nn][3] *= corr_g8;
        }

        #pragma unroll
        for (int jj = 0; jj < 4; jj++) {
            uint32_t pa0[4] = {p[4 * jj][0],     p[4 * jj][1],
                               p[4 * jj + 1][0], p[4 * jj + 1][1]};
            uint32_t pa1[4] = {p[4 * jj + 2][0], p[4 * jj + 2][1],
                               p[4 * jj + 3][0], p[4 * jj + 3][1]};
            int krow = jj * 32 + (lane >> 3) * 8 + (lane & 7);
            #pragma unroll
            for (int nn = 0; nn < 16; nn++) {
                uint32_t r4[4];
                ldsm_x4_t(r4, vsb + (uint32_t)((krow * FA_STRH + nn * 8) * 2));
                mma_f16(o[nn], pa0, r4[0], r4[1]);
                mma_f16(o[nn], pa1, r4[2], r4[3]);
            }
        }

        __syncthreads();
        buf ^= 1;
    }

    float il_g = 1.0f / l_g, il_g8 = 1.0f / l_g8;
    long orow = (long)b * SS + qb * FA_BM + woff + g;
    __half* obase = g_ah + orow * (HH * HDD) + h * HDD;
    #pragma unroll
    for (int nn = 0; nn < 16; nn++) {
        int col = nn * 8 + 2 * t;
        *(uint32_t*)&obase[col] = pack_h2(o[nn][0] * il_g, o[nn][1] * il_g);
        *(uint32_t*)&obase[(long)8 * (HH * HDD) + col] =
            pack_h2(o[nn][2] * il_g8, o[nn][3] * il_g8);
    }
}

// ================= launcher =================================================
extern "C" void kernel_launch(void* const* d_in, const int* in_sizes, int n_in,
                              void* d_out, int out_size)
{
    const float* x    = (const float*)d_in[0];
    const float* cosp = (const float*)d_in[1];
    const float* sinp = (const float*)d_in[2];
    const float* wq   = (const float*)d_in[3];
    const float* wk   = (const float*)d_in[4];
    const float* wv   = (const float*)d_in[5];
    const float* wo   = (const float*)d_in[6];
    float* out = (float*)d_out;

    __half *pxh, *pwqh, *pwoh, *pqh, *pah;
    cudaGetSymbolAddress((void**)&pxh,  g_xh);
    cudaGetSymbolAddress((void**)&pwqh, g_wqh);
    cudaGetSymbolAddress((void**)&pwoh, g_woh);
    cudaGetSymbolAddress((void**)&pqh,  g_qh);
    cudaGetSymbolAddress((void**)&pah,  g_ah);

    const int M = BB * SS;  // 8192
    // 1/sqrt(128) * log2(e): scores arrive in log2 domain
    const float scale = 0.08838834764831845f * 1.4426950408889634f;

    {
        unsigned blks = (unsigned)((N8_TOT + 255) / 256);
        cvt_all_kernel<<<blks, 256>>>(x, wq, wo, wk, wv, scale);
    }

    cudaFuncSetAttribute(gemm_hp<true, true>,
                         cudaFuncAttributeMaxDynamicSharedMemorySize, GSMEM);
    cudaFuncSetAttribute(gemm_hp<false, false>,
                         cudaFuncAttributeMaxDynamicSharedMemorySize, GSMEM);

    // fused q + kv projection: grid (24, 64), 2 CTAs/SM
    gemm_hp<true, true><<<dim3((DD + KVSTR) / 128, M / 128), 256, GSMEM>>>(
        pxh, pwqh, pqh, M, DD, DD);

    {
        long total = (long)BB * SS * (HH + KVHH) * 8;
        int blocks = (int)((total + 255) / 256);
        rope_h_kernel<<<blocks, 256>>>(cosp, sinp);
    }

    {
        cudaFuncSetAttribute(flash_attn_hp, cudaFuncAttributeMaxDynamicSharedMemorySize,
                             FA_SMEMB);
        flash_attn_hp<<<dim3(SS / FA_BM, HH, BB), 256, FA_SMEMB>>>();
    }

    // Output projection (float out), grid (16, 64)
    gemm_hp<false, false><<<dim3(DD / 128, M / 128), 256, GSMEM>>>(
        pah, pwoh, out, M, DD, DD);
}